// round 10
// baseline (speedup 1.0000x reference)
#include <cuda_runtime.h>
#include <cuda_fp16.h>
#include <cstdint>

#define Bb     2
#define CIN    32
#define COUT   64
#define KK     9
#define HH     256
#define WW     512
#define HWSZ   (HH*WW)        // 131072
#define OHW    (HH*WW)        // 131072
#define CK     (CIN*KK)       // 288
#define NKS16  (CK/16)        // 18 k16-steps

#define TPIX   16             // pixels per tile
#define NCOLS  32             // gemm N = 16 pix * 2 batch
#define SLH    20             // sB half2-word stride per col (20%32==4*odd -> conflict-free)
#define NTHR   128

// scratch: x transposed to [B, H*W, C] (fp32); weights packed as fp16 m16n8k16 A-fragments
__device__ __align__(16) float    g_xt[(size_t)Bb*HWSZ*CIN];
__device__ __align__(16) uint32_t g_wfrag[NKS16*4*32*4];   // [mg4][ks18][lane32][reg4] half2

__device__ __forceinline__ uint32_t h2u(__half2 h) {
    union { __half2 h; uint32_t u; } c; c.h = h; return c.u;
}

// ------- transpose x: [B,C,HW] -> [B,HW,C], float4 both sides; wt fused on y==2 -------
__global__ void transpose_kernel(const float* __restrict__ x,
                                 const float* __restrict__ w) {
    __shared__ float tile[32][36];
    int b   = blockIdx.y;
    int tid = threadIdx.x;
    if (b == 2) {
        // weights: W[o][c][k] -> fp16 A-frag layout [mg][ks][lane][reg], reg = half2
        int i = blockIdx.x*256 + tid;
        if (i < NKS16*4*32*4) {
            int j    = i & 3;
            int lane = (i >> 2) & 31;
            int ks   = (i >> 7) % NKS16;
            int mg   = (i >> 7) / NKS16;
            int o  = mg*16 + (lane >> 2) + 8*(j & 1);
            int cc = (ks & 1)*16 + (lane & 3)*2 + ((j >> 1) & 1)*8;
            int k  = ks >> 1;
            float v0 = w[(o*CIN + cc    )*KK + k];
            float v1 = w[(o*CIN + cc + 1)*KK + k];
            g_wfrag[i] = h2u(__floats2half2_rn(v0, v1));
        }
        return;
    }
    int hw0 = blockIdx.x * 32;
    {
        int c = tid >> 3, q = tid & 7;
        float4 v = ((const float4*)x)[(((size_t)(b*CIN + c))*HWSZ + hw0)/4 + q];
        *(float4*)&tile[c][q*4] = v;
    }
    __syncthreads();
    {
        int hw = tid & 31, cq = tid >> 5;
        ((float4*)g_xt)[((size_t)b*HWSZ + hw0 + hw)*8 + cq] =
            make_float4(tile[cq*4+0][hw], tile[cq*4+1][hw],
                        tile[cq*4+2][hw], tile[cq*4+3][hw]);
    }
}

// ---------------- main: deep-pipelined gather + fp16 mma.sync, 5 CTAs/SM ----------------
__global__ void __launch_bounds__(NTHR, 5)
mapped_conv_kernel(const float* __restrict__ bias,
                   const float* __restrict__ smap,
                   float* __restrict__ out)
{
    __shared__ uint32_t sB[2*NCOLS*SLH];   // 2560 u32: double-buffered fp16 sampled tile
    __shared__ int4   sIdx4[TPIX*KK];      // 144
    __shared__ float4 sWgt4[TPIX*KK];      // 144
    __shared__ float  sBias[COUT];

    const int tid  = threadIdx.x;
    const int w    = tid >> 5;             // 0..3
    const int lane = tid & 31;
    const int pix0 = blockIdx.x * TPIX;

    if (tid < COUT) sBias[tid] = bias[tid];

    // bilinear tables: task t = p*9+k, 144 tasks
    for (int t = tid; t < TPIX*KK; t += NTHR) {
        int p = t / KK, k = t - p*KK;
        float2 sxy = ((const float2*)smap)[(pix0 + p)*KK + k];
        float bx = floorf(sxy.x), by = floorf(sxy.y);
        float fx = sxy.x - bx,    fy = sxy.y - by;
        int x0 = (int)bx, y0 = (int)by;
        int x0c = min(max(x0, 0), WW-1);
        int x1c = min(x0 + 1, WW-1);
        int y0c = min(max(y0, 0), HH-1);
        int y1c = min(y0 + 1, HH-1);
        sIdx4[t] = make_int4(y0c*WW + x0c, y0c*WW + x1c,
                             y1c*WW + x0c, y1c*WW + x1c);
        sWgt4[t] = make_float4((1.f-fx)*(1.f-fy), fx*(1.f-fy),
                               (1.f-fx)*fy,       fx*fy);
    }

    // gather mapping: warp w -> 8 cols; col = b*16 + p
    const int gb_b  = w >> 1;
    const int gcol0 = w * 8;
    const int gp0   = (w & 1) * 8;
    const int cq    = lane & 7;
    const int cs    = lane >> 3;
    const float4* __restrict__ gxb4 = (const float4*)g_xt + (size_t)gb_b*HWSZ*8 + cq;

    // mma mapping: warp = mw (rows mw*16..+15), all 32 cols
    const int mw = w;
    uint32_t bOff[4];
#pragma unroll
    for (int g = 0; g < 4; g++)
        bOff[g] = (uint32_t)(g*8 + (lane >> 2))*SLH + (lane & 3);

    const uint4* __restrict__ gw4 =
        (const uint4*)g_wfrag + (uint32_t)(mw*NKS16)*32 + lane;

    float d[4][4];
#pragma unroll
    for (int g = 0; g < 4; g++)
#pragma unroll
        for (int j = 0; j < 4; j++) d[g][j] = 0.f;

    float4 vs[2][4];     // [col-iter][corner]
    uint4  Acur[2], Anx[2];

    __syncthreads();     // tables ready

    // ---- prologue: gather+store tap 0; issue tap 1 loads; prefetch A(0)
#pragma unroll
    for (int i = 0; i < 2; i++) {
        int p = gp0 + i*4 + cs;
        int4 id = sIdx4[p*KK];
        vs[i][0] = gxb4[(size_t)id.x*8];
        vs[i][1] = gxb4[(size_t)id.y*8];
        vs[i][2] = gxb4[(size_t)id.z*8];
        vs[i][3] = gxb4[(size_t)id.w*8];
    }
#pragma unroll
    for (int h = 0; h < 2; h++) Anx[h] = gw4[h*32];
#pragma unroll
    for (int i = 0; i < 2; i++) {
        int p   = gp0 + i*4 + cs;
        int col = gcol0 + i*4 + cs;
        float4 wt = sWgt4[p*KK];
        float ax = wt.x*vs[i][0].x + wt.y*vs[i][1].x + wt.z*vs[i][2].x + wt.w*vs[i][3].x;
        float ay = wt.x*vs[i][0].y + wt.y*vs[i][1].y + wt.z*vs[i][2].y + wt.w*vs[i][3].y;
        float az = wt.x*vs[i][0].z + wt.y*vs[i][1].z + wt.z*vs[i][2].z + wt.w*vs[i][3].z;
        float aw = wt.x*vs[i][0].w + wt.y*vs[i][1].w + wt.z*vs[i][2].w + wt.w*vs[i][3].w;
        *(uint2*)&sB[(uint32_t)col*SLH + cq*2] =
            make_uint2(h2u(__floats2half2_rn(ax, ay)), h2u(__floats2half2_rn(az, aw)));
    }
    // issue tap-1 loads (land during first MMA)
#pragma unroll
    for (int i = 0; i < 2; i++) {
        int p = gp0 + i*4 + cs;
        int4 id = sIdx4[p*KK + 1];
        vs[i][0] = gxb4[(size_t)id.x*8];
        vs[i][1] = gxb4[(size_t)id.y*8];
        vs[i][2] = gxb4[(size_t)id.z*8];
        vs[i][3] = gxb4[(size_t)id.w*8];
    }
    __syncthreads();

    // ---- main loop: 9 taps, deep pipeline
#pragma unroll
    for (int k = 0; k < KK; k++) {
#pragma unroll
        for (int h = 0; h < 2; h++) Acur[h] = Anx[h];
        if (k + 1 < KK) {
#pragma unroll
            for (int h = 0; h < 2; h++) Anx[h] = gw4[((k+1)*2 + h)*32];
        }
        // MMA tap k (buf k&1): 2 k16-steps x 4 n-groups
        {
            const uint32_t bufb = (uint32_t)(k & 1) * (NCOLS*SLH);
#pragma unroll
            for (int h = 0; h < 2; h++) {
#pragma unroll
                for (int g = 0; g < 4; g++) {
                    uint32_t b0 = sB[bufb + bOff[g] + h*8];
                    uint32_t b1 = sB[bufb + bOff[g] + h*8 + 4];
                    asm volatile(
                        "mma.sync.aligned.m16n8k16.row.col.f32.f16.f16.f32 "
                        "{%0,%1,%2,%3}, {%4,%5,%6,%7}, {%8,%9}, {%0,%1,%2,%3};"
                        : "+f"(d[g][0]), "+f"(d[g][1]), "+f"(d[g][2]), "+f"(d[g][3])
                        : "r"(Acur[h].x), "r"(Acur[h].y),
                          "r"(Acur[h].z), "r"(Acur[h].w), "r"(b0), "r"(b1));
                }
            }
        }
        if (k + 1 < KK) {
            // combine tap k+1 (loads issued one full stage ago) + store
            uint32_t* dstb = sB + (uint32_t)((k + 1) & 1)*(NCOLS*SLH);
#pragma unroll
            for (int i = 0; i < 2; i++) {
                int p   = gp0 + i*4 + cs;
                int col = gcol0 + i*4 + cs;
                float4 wt = sWgt4[p*KK + k + 1];
                float ax = wt.x*vs[i][0].x + wt.y*vs[i][1].x + wt.z*vs[i][2].x + wt.w*vs[i][3].x;
                float ay = wt.x*vs[i][0].y + wt.y*vs[i][1].y + wt.z*vs[i][2].y + wt.w*vs[i][3].y;
                float az = wt.x*vs[i][0].z + wt.y*vs[i][1].z + wt.z*vs[i][2].z + wt.w*vs[i][3].z;
                float aw = wt.x*vs[i][0].w + wt.y*vs[i][1].w + wt.z*vs[i][2].w + wt.w*vs[i][3].w;
                *(uint2*)&dstb[(uint32_t)col*SLH + cq*2] =
                    make_uint2(h2u(__floats2half2_rn(ax, ay)),
                               h2u(__floats2half2_rn(az, aw)));
            }
            // issue tap k+2 loads into freed vs (in flight across sync + next MMA)
            if (k + 2 < KK) {
#pragma unroll
                for (int i = 0; i < 2; i++) {
                    int p = gp0 + i*4 + cs;
                    int4 id = sIdx4[p*KK + k + 2];
                    vs[i][0] = gxb4[(size_t)id.x*8];
                    vs[i][1] = gxb4[(size_t)id.y*8];
                    vs[i][2] = gxb4[(size_t)id.z*8];
                    vs[i][3] = gxb4[(size_t)id.w*8];
                }
            }
            __syncthreads();
        }
    }

    // ---- epilogue: D row = output channel o, col = (b, pixel)
    {
        int o0 = mw*16 + (lane >> 2);
        float bias0 = sBias[o0];
        float bias1 = sBias[o0 + 8];
#pragma unroll
        for (int g = 0; g < 4; g++) {
            int n  = g*8 + (lane & 3)*2;
            int bb = n >> 4;
            int p  = n & 15;
            float* op = out + ((size_t)(bb*COUT + o0))*OHW + pix0 + p;
            *(float2*)op = make_float2(d[g][0] + bias0, d[g][1] + bias0);
            *(float2*)(op + (size_t)8*OHW) = make_float2(d[g][2] + bias1, d[g][3] + bias1);
        }
    }
}

extern "C" void kernel_launch(void* const* d_in, const int* in_sizes, int n_in,
                              void* d_out, int out_size) {
    const float* x    = (const float*)d_in[0];
    const float* w    = (const float*)d_in[1];
    const float* bias = (const float*)d_in[2];
    const float* smap = (const float*)d_in[3];
    float* out = (float*)d_out;

    transpose_kernel<<<dim3(HWSZ/32, 3), 256>>>(x, w);   // y==2 slice does weights
    mapped_conv_kernel<<<OHW/TPIX, NTHR>>>(bias, smap, out);
}